// round 1
// baseline (speedup 1.0000x reference)
#include <cuda_runtime.h>
#include <cstdint>
#include <math.h>

// Problem dims
#define TT 128
#define NN 64
#define DD 512
#define HH 512
#define G3 1536   // 3*H

typedef unsigned long long ull;

// ---------------- packed f32x2 helpers ----------------
__device__ __forceinline__ ull fma2(ull a, ull b, ull c) {
    ull d;
    asm("fma.rn.f32x2 %0, %1, %2, %3;" : "=l"(d) : "l"(a), "l"(b), "l"(c));
    return d;
}
__device__ __forceinline__ float lo32(ull v) { return __uint_as_float((unsigned)(v & 0xffffffffu)); }
__device__ __forceinline__ float hi32(ull v) { return __uint_as_float((unsigned)(v >> 32)); }
__device__ __forceinline__ ull pack2(float x, float y) {
    return (((ull)__float_as_uint(y)) << 32) | (ull)__float_as_uint(x);
}

// ---------------- global scratch ----------------
__device__ float    g_gi[TT * NN * G3];   // 48MB: precomputed input projections
__device__ unsigned g_bar;                // grid barrier counter (reset by gemm kernel)

// =====================================================================
// Kernel 1: gi[m, g] = sum_k x[m,k] * w_ih[g,k] + b_ih[g]
// M=8192, N(g)=1536, K=512.  Tiles: BM=128, BN=64, BK=32. 256 threads.
// Thread tile 8x4, columns/rows strided by 16 for conflict-free smem.
// =====================================================================
__global__ void __launch_bounds__(256) gemm_gi_kernel(
    const float* __restrict__ x,
    const float* __restrict__ w_ih,
    const float* __restrict__ b_ih)
{
    // reset the grid barrier for the scan kernel (runs later in stream order)
    if (blockIdx.x == 0 && blockIdx.y == 0 && threadIdx.x == 0) g_bar = 0u;

    __shared__ ull As[128 * 17];  // 128 rows x 16 f2 (+1 pad)
    __shared__ ull Bs[64 * 17];

    const int tid = threadIdx.x;
    const int m0 = blockIdx.y * 128;
    const int g0 = blockIdx.x * 64;
    const int tx = tid & 15;   // column group
    const int ty = tid >> 4;   // row group

    ull acc[8][4];
#pragma unroll
    for (int i = 0; i < 8; i++)
#pragma unroll
        for (int j = 0; j < 4; j++) acc[i][j] = 0ull;

    for (int k0 = 0; k0 < DD; k0 += 32) {
        // load A tile: 128 rows x 32 k  (1024 float4 slots)
#pragma unroll
        for (int i = 0; i < 4; i++) {
            int s = tid + i * 256;
            int row = s >> 3, kq = s & 7;
            float4 v = *reinterpret_cast<const float4*>(&x[(size_t)(m0 + row) * DD + k0 + kq * 4]);
            As[row * 17 + kq * 2]     = pack2(v.x, v.y);
            As[row * 17 + kq * 2 + 1] = pack2(v.z, v.w);
        }
        // load B tile: 64 rows x 32 k (512 float4 slots)
#pragma unroll
        for (int i = 0; i < 2; i++) {
            int s = tid + i * 256;
            int row = s >> 3, kq = s & 7;
            float4 v = *reinterpret_cast<const float4*>(&w_ih[(size_t)(g0 + row) * DD + k0 + kq * 4]);
            Bs[row * 17 + kq * 2]     = pack2(v.x, v.y);
            Bs[row * 17 + kq * 2 + 1] = pack2(v.z, v.w);
        }
        __syncthreads();

#pragma unroll
        for (int kk = 0; kk < 16; kk++) {
            ull a[8], b[4];
#pragma unroll
            for (int i = 0; i < 8; i++) a[i] = As[(ty + 16 * i) * 17 + kk];
#pragma unroll
            for (int j = 0; j < 4; j++) b[j] = Bs[(tx + 16 * j) * 17 + kk];
#pragma unroll
            for (int i = 0; i < 8; i++)
#pragma unroll
                for (int j = 0; j < 4; j++)
                    acc[i][j] = fma2(a[i], b[j], acc[i][j]);
        }
        __syncthreads();
    }

#pragma unroll
    for (int i = 0; i < 8; i++) {
        int m = m0 + ty + 16 * i;
#pragma unroll
        for (int j = 0; j < 4; j++) {
            int g = g0 + tx + 16 * j;
            g_gi[(size_t)m * G3 + g] = lo32(acc[i][j]) + hi32(acc[i][j]) + b_ih[g];
        }
    }
}

// =====================================================================
// Kernel 2: persistent GRU scan.
// Grid: 128 CTAs = 2 row-blocks (32 rows of N=64) x 64 dim-blocks (8 of H=512).
// 128 threads: tid%16 -> row pair {r, r+16}, tid/16 -> one h-dim (3 gates).
// w_hh slice (24 rows x 512) stays in smem for all 128 steps.
// Per step: stage masked h (32x512) in smem, packed-f32x2 dot products,
// gate math, write h_t to out, global spin barrier.
// =====================================================================
__global__ void __launch_bounds__(128) gru_scan_kernel(
    const float* __restrict__ hxs,
    const float* __restrict__ masks,
    const float* __restrict__ w_hh,
    const float* __restrict__ b_hh,
    float* __restrict__ out)   // d_out base
{
    extern __shared__ float smem[];
    float* hs = smem;                       // [32][514]  (pad 2 -> conflict-free ull reads)
    float* ws = smem + 32 * 514;            // [3][8][512]

    const int tid = threadIdx.x;
    const int jb = blockIdx.x & 63;         // dim block: dims jb*8 .. jb*8+7
    const int rb = blockIdx.x >> 6;         // row block: rows rb*32 .. rb*32+31
    const int r2 = tid & 15;                // row pair base
    const int dl = tid >> 4;                // 0..7 local dim
    const int dim_g = jb * 8 + dl;

    // ---- stage w_hh slice once: rows (g*512 + dim) for g=0..2, dim in block ----
    for (int i = 0; i < 24; i++) {
        int s = tid + i * 128;              // over 24 rows x 128 float4
        int lrow = s >> 7;                  // 0..23
        int kq = s & 127;
        int g = lrow >> 3;
        int dloc = lrow & 7;
        float4 v = *reinterpret_cast<const float4*>(
            &w_hh[(size_t)(g * HH + jb * 8 + dloc) * HH + kq * 4]);
        *reinterpret_cast<float4*>(&ws[(size_t)(g * 8 + dloc) * HH + kq * 4]) = v;
    }
    const float bh_r = b_hh[dim_g];
    const float bh_z = b_hh[HH + dim_g];
    const float bh_n = b_hh[2 * HH + dim_g];

    const ull* ws_u = reinterpret_cast<const ull*>(ws);
    const int wr_off = (0 * 8 + dl) * 256;
    const int wz_off = (1 * 8 + dl) * 256;
    const int wn_off = (2 * 8 + dl) * 256;

    const ull* hs_u = reinterpret_cast<const ull*>(hs);
    const int h0 = r2 * 257;
    const int h1 = (r2 + 16) * 257;

    unsigned bar_tgt = 0;

    for (int t = 0; t < TT; t++) {
        const float* hprev = (t == 0) ? hxs : (out + (size_t)(t - 1) * NN * HH);

        // ---- stage masked h: 32 rows x 512 ----
#pragma unroll 8
        for (int i = 0; i < 32; i++) {
            int s = tid + i * 128;          // over 32 rows x 128 float4
            int row = s >> 7;
            int kq = s & 127;
            int n = rb * 32 + row;
            float m = masks[t * NN + n];
            float4 v = __ldcg(reinterpret_cast<const float4*>(&hprev[(size_t)n * HH + kq * 4]));
            float* dst = &hs[row * 514 + kq * 4];
            dst[0] = v.x * m; dst[1] = v.y * m; dst[2] = v.z * m; dst[3] = v.w * m;
        }
        __syncthreads();

        // ---- dot products (packed over k) ----
        ull ar0 = 0, az0 = 0, an0 = 0, ar1 = 0, az1 = 0, an1 = 0;
#pragma unroll 8
        for (int k2 = 0; k2 < 256; k2++) {
            ull a0 = hs_u[h0 + k2];
            ull a1 = hs_u[h1 + k2];
            ull wr = ws_u[wr_off + k2];
            ull wz = ws_u[wz_off + k2];
            ull wn = ws_u[wn_off + k2];
            ar0 = fma2(a0, wr, ar0); az0 = fma2(a0, wz, az0); an0 = fma2(a0, wn, an0);
            ar1 = fma2(a1, wr, ar1); az1 = fma2(a1, wz, az1); an1 = fma2(a1, wn, an1);
        }

        // ---- gates + store ----
#pragma unroll
        for (int rr = 0; rr < 2; rr++) {
            int rloc = r2 + rr * 16;
            int n = rb * 32 + rloc;
            float ghr = (rr ? (lo32(ar1) + hi32(ar1)) : (lo32(ar0) + hi32(ar0))) + bh_r;
            float ghz = (rr ? (lo32(az1) + hi32(az1)) : (lo32(az0) + hi32(az0))) + bh_z;
            float ghn = (rr ? (lo32(an1) + hi32(an1)) : (lo32(an0) + hi32(an0))) + bh_n;

            const float* gi_t = g_gi + (size_t)(t * NN + n) * G3;
            float ir = gi_t[dim_g];
            float iz = gi_t[HH + dim_g];
            float inn = gi_t[2 * HH + dim_g];

            float r = 1.0f / (1.0f + expf(-(ir + ghr)));
            float z = 1.0f / (1.0f + expf(-(iz + ghz)));
            float nc = tanhf(inn + r * ghn);
            float hval = hs[rloc * 514 + dim_g];       // masked h
            float hnew = (1.0f - z) * nc + z * hval;

            out[(size_t)(t * NN + n) * HH + dim_g] = hnew;
            if (t == TT - 1)
                out[(size_t)TT * NN * HH + (size_t)n * HH + dim_g] = hnew;  // h_last
        }

        // ---- grid barrier ----
        __syncthreads();
        __threadfence();
        bar_tgt += gridDim.x;
        if (tid == 0) {
            atomicAdd(&g_bar, 1u);
            while (atomicAdd(&g_bar, 0u) < bar_tgt) { __nanosleep(64); }
            __threadfence();
        }
        __syncthreads();
    }
}

// =====================================================================
extern "C" void kernel_launch(void* const* d_in, const int* in_sizes, int n_in,
                              void* d_out, int out_size)
{
    const float* x      = (const float*)d_in[0];
    const float* hxs    = (const float*)d_in[1];
    const float* hxs_1  = (const float*)d_in[2];
    const float* masks  = (const float*)d_in[3];
    const float* w_ih   = (const float*)d_in[4];
    const float* w_hh   = (const float*)d_in[5];
    const float* b_ih   = (const float*)d_in[6];
    const float* b_hh   = (const float*)d_in[7];
    float* out = (float*)d_out;

    // third output: hxs_1 passthrough
    cudaMemcpyAsync(out + (size_t)(TT * NN + NN) * HH, hxs_1,
                    (size_t)NN * HH * sizeof(float), cudaMemcpyDeviceToDevice);

    // input projections (also resets the grid barrier)
    dim3 g1(G3 / 64, (TT * NN) / 128);   // (24, 64)
    gemm_gi_kernel<<<g1, 256>>>(x, w_ih, b_ih);

    // persistent scan
    size_t shmem = (size_t)(32 * 514 + 3 * 8 * HH) * sizeof(float);  // 114,944 B
    cudaFuncSetAttribute(gru_scan_kernel,
                         cudaFuncAttributeMaxDynamicSharedMemorySize, (int)shmem);
    gru_scan_kernel<<<128, 128, shmem>>>(hxs, masks, w_hh, b_hh, out);
}

// round 2
// speedup vs baseline: 1.5219x; 1.5219x over previous
#include <cuda_runtime.h>
#include <cstdint>
#include <math.h>

// Problem dims
#define TT 128
#define NN 64
#define DD 512
#define HH 512
#define G3 1536   // 3*H
#define SCAN_CTAS 128

typedef unsigned long long ull;

// ---------------- packed f32x2 helpers ----------------
__device__ __forceinline__ ull fma2(ull a, ull b, ull c) {
    ull d;
    asm("fma.rn.f32x2 %0, %1, %2, %3;" : "=l"(d) : "l"(a), "l"(b), "l"(c));
    return d;
}
__device__ __forceinline__ float lo32(ull v) { return __uint_as_float((unsigned)(v & 0xffffffffu)); }
__device__ __forceinline__ float hi32(ull v) { return __uint_as_float((unsigned)(v >> 32)); }
__device__ __forceinline__ ull pack2(float x, float y) {
    return (((ull)__float_as_uint(y)) << 32) | (ull)__float_as_uint(x);
}

// ---------------- global scratch ----------------
// gi stored TRANSPOSED: g_gi[g * 8192 + m]  (g in [0,1536), m = t*64+n)
__device__ float g_gi[(size_t)G3 * TT * NN];

struct __align__(128) PadU { unsigned v; unsigned pad[31]; };
__device__ PadU g_count;
__device__ PadU g_epoch;

// =====================================================================
// Kernel 1: gi^T[g, m] = sum_k x[m,k] * w_ih[g,k] + b_ih[g]
// Tiles 64(g) x 64(m), BK=32, 256 threads, 4x4 ull thread tile.
// Store side coalesced in m (tx -> consecutive m).
// =====================================================================
__global__ void __launch_bounds__(256, 2) gemm_gi_kernel(
    const float* __restrict__ x,
    const float* __restrict__ w_ih,
    const float* __restrict__ b_ih)
{
    if (blockIdx.x == 0 && blockIdx.y == 0 && threadIdx.x == 0) {
        g_count.v = 0;
        g_epoch.v = 0;
    }

    __shared__ ull Gs[64 * 17];   // w_ih rows (g), 16 f2 per row + pad
    __shared__ ull Ms[64 * 17];   // x rows (m)

    const int tid = threadIdx.x;
    const int g0 = blockIdx.x * 64;
    const int m0 = blockIdx.y * 64;
    const int tx = tid & 15;      // -> m group
    const int ty = tid >> 4;      // -> g group

    ull acc[4][4];
#pragma unroll
    for (int i = 0; i < 4; i++)
#pragma unroll
        for (int j = 0; j < 4; j++) acc[i][j] = 0ull;

    for (int k0 = 0; k0 < DD; k0 += 32) {
#pragma unroll
        for (int i = 0; i < 2; i++) {
            int s = tid + i * 256;
            int row = s >> 3, kq = s & 7;
            float4 vg = *reinterpret_cast<const float4*>(&w_ih[(size_t)(g0 + row) * DD + k0 + kq * 4]);
            Gs[row * 17 + kq * 2]     = pack2(vg.x, vg.y);
            Gs[row * 17 + kq * 2 + 1] = pack2(vg.z, vg.w);
            float4 vm = *reinterpret_cast<const float4*>(&x[(size_t)(m0 + row) * DD + k0 + kq * 4]);
            Ms[row * 17 + kq * 2]     = pack2(vm.x, vm.y);
            Ms[row * 17 + kq * 2 + 1] = pack2(vm.z, vm.w);
        }
        __syncthreads();

#pragma unroll
        for (int kk = 0; kk < 16; kk++) {
            ull a[4], b[4];
#pragma unroll
            for (int i = 0; i < 4; i++) a[i] = Gs[(ty + 16 * i) * 17 + kk];
#pragma unroll
            for (int j = 0; j < 4; j++) b[j] = Ms[(tx + 16 * j) * 17 + kk];
#pragma unroll
            for (int i = 0; i < 4; i++)
#pragma unroll
                for (int j = 0; j < 4; j++)
                    acc[i][j] = fma2(a[i], b[j], acc[i][j]);
        }
        __syncthreads();
    }

#pragma unroll
    for (int i = 0; i < 4; i++) {
        int g = g0 + ty + 16 * i;
        float bias = b_ih[g];
#pragma unroll
        for (int j = 0; j < 4; j++) {
            int m = m0 + tx + 16 * j;
            g_gi[(size_t)g * (TT * NN) + m] = lo32(acc[i][j]) + hi32(acc[i][j]) + bias;
        }
    }
}

// =====================================================================
// Kernel 2: persistent GRU scan.
// 128 CTAs: rb = blockIdx>>6 (rows rb*32..+31), jb = blockIdx&63 (dims jb*8..+7).
// 256 threads: kh = tid>>7 (K half), r2 = tid&15 (row pair), dl = (tid>>4)&7.
// w_hh slice resident in smem; h staged unmasked each step; mask folded into
// the 6 dot results + hval in the epilogue.
// Grid barrier: atom.add.release arrival + ld.acquire epoch polling.
// =====================================================================
__global__ void __launch_bounds__(256) gru_scan_kernel(
    const float* __restrict__ hxs,
    const float* __restrict__ masks,
    const float* __restrict__ w_hh,
    const float* __restrict__ b_hh,
    float* __restrict__ out)
{
    extern __shared__ float smem[];
    float* hs  = smem;                            // [32][514]
    float* ws  = smem + 32 * 514;                 // [24][516]
    float* red = smem + 32 * 514 + 24 * 516;      // [128][6]

    const int tid = threadIdx.x;
    const int jb = blockIdx.x & 63;
    const int rb = blockIdx.x >> 6;
    const int n0 = rb * 32;
    const int low7 = tid & 127;
    const int kh = tid >> 7;          // 0/1: K half
    const int r2 = low7 & 15;
    const int dl = low7 >> 4;         // 0..7
    const int dim_g = jb * 8 + dl;

    // ---- stage w_hh slice once: rows g*512 + jb*8+dloc, g=0..2 ----
#pragma unroll
    for (int i = 0; i < 12; i++) {
        int s = tid + i * 256;        // 24 rows x 128 float4 = 3072
        int lrow = s >> 7;            // 0..23
        int kq = s & 127;
        int g = lrow >> 3;
        int dloc = lrow & 7;
        float4 v = *reinterpret_cast<const float4*>(
            &w_hh[(size_t)(g * HH + jb * 8 + dloc) * HH + kq * 4]);
        *reinterpret_cast<float4*>(&ws[lrow * 516 + kq * 4]) = v;
    }
    const float bh_r = b_hh[dim_g];
    const float bh_z = b_hh[HH + dim_g];
    const float bh_n = b_hh[2 * HH + dim_g];

    const ull* hs_u = reinterpret_cast<const ull*>(hs);
    const ull* ws_u = reinterpret_cast<const ull*>(ws);
    const int h0 = r2 * 257 + kh * 128;
    const int h1 = h0 + 16 * 257;
    const int wr = (dl) * 258 + kh * 128;
    const int wz = (8 + dl) * 258 + kh * 128;
    const int wn = (16 + dl) * 258 + kh * 128;

    for (int t = 0; t < TT; t++) {
        const float* hprev = (t == 0) ? hxs : (out + (size_t)(t - 1) * NN * HH);

        // ---- stage h (unmasked): 32 rows x 512 floats ----
#pragma unroll
        for (int i = 0; i < 16; i++) {
            int s = tid + i * 256;    // 32 rows x 128 float4 = 4096
            int row = s >> 7;
            int kq = s & 127;
            float4 v = __ldcg(reinterpret_cast<const float4*>(
                &hprev[(size_t)(n0 + row) * HH + kq * 4]));
            float2* dst = reinterpret_cast<float2*>(&hs[row * 514 + kq * 4]);
            dst[0] = make_float2(v.x, v.y);
            dst[1] = make_float2(v.z, v.w);
        }
        __syncthreads();

        // ---- half-K dot products ----
        ull ar0 = 0, az0 = 0, an0 = 0, ar1 = 0, az1 = 0, an1 = 0;
#pragma unroll 8
        for (int k = 0; k < 128; k++) {
            ull a0 = hs_u[h0 + k];
            ull a1 = hs_u[h1 + k];
            ull vr = ws_u[wr + k];
            ull vz = ws_u[wz + k];
            ull vn = ws_u[wn + k];
            ar0 = fma2(a0, vr, ar0); az0 = fma2(a0, vz, az0); an0 = fma2(a0, vn, an0);
            ar1 = fma2(a1, vr, ar1); az1 = fma2(a1, vz, az1); an1 = fma2(a1, vn, an1);
        }
        float p[6];
        p[0] = lo32(ar0) + hi32(ar0);
        p[1] = lo32(az0) + hi32(az0);
        p[2] = lo32(an0) + hi32(an0);
        p[3] = lo32(ar1) + hi32(ar1);
        p[4] = lo32(az1) + hi32(az1);
        p[5] = lo32(an1) + hi32(an1);

        if (kh == 1) {
#pragma unroll
            for (int c = 0; c < 6; c++) red[low7 * 6 + c] = p[c];
        }
        __syncthreads();

        if (kh == 0) {
#pragma unroll
            for (int c = 0; c < 6; c++) p[c] += red[low7 * 6 + c];

#pragma unroll
            for (int rr = 0; rr < 2; rr++) {
                int rloc = r2 + rr * 16;
                int n = n0 + rloc;
                float m = masks[t * NN + n];
                float ghr = p[rr * 3 + 0] * m + bh_r;
                float ghz = p[rr * 3 + 1] * m + bh_z;
                float ghn = p[rr * 3 + 2] * m + bh_n;

                int mm = t * NN + n;
                float ir  = g_gi[(size_t)(0 * HH + dim_g) * (TT * NN) + mm];
                float iz  = g_gi[(size_t)(1 * HH + dim_g) * (TT * NN) + mm];
                float inn = g_gi[(size_t)(2 * HH + dim_g) * (TT * NN) + mm];

                float r = 1.0f / (1.0f + expf(-(ir + ghr)));
                float z = 1.0f / (1.0f + expf(-(iz + ghz)));
                float nc = tanhf(inn + r * ghn);
                float hval = m * hs[rloc * 514 + dim_g];
                float hnew = (1.0f - z) * nc + z * hval;

                out[(size_t)mm * HH + dim_g] = hnew;
                if (t == TT - 1)
                    out[(size_t)TT * NN * HH + (size_t)n * HH + dim_g] = hnew;
            }
        }

        // ---- grid barrier (skip after last step) ----
        if (t < TT - 1) {
            __syncthreads();
            if (tid == 0) {
                unsigned old;
                asm volatile("atom.add.release.gpu.global.u32 %0, [%1], 1;"
                             : "=r"(old) : "l"(&g_count.v) : "memory");
                unsigned target = (unsigned)(t + 1);
                if (old == SCAN_CTAS - 1) {
                    g_count.v = 0;
                    asm volatile("st.release.gpu.global.u32 [%0], %1;"
                                 :: "l"(&g_epoch.v), "r"(target) : "memory");
                } else {
                    unsigned e;
                    do {
                        asm volatile("ld.acquire.gpu.global.u32 %0, [%1];"
                                     : "=r"(e) : "l"(&g_epoch.v) : "memory");
                    } while (e < target);
                }
            }
            __syncthreads();
        }
    }
}

// =====================================================================
extern "C" void kernel_launch(void* const* d_in, const int* in_sizes, int n_in,
                              void* d_out, int out_size)
{
    const float* x      = (const float*)d_in[0];
    const float* hxs    = (const float*)d_in[1];
    const float* hxs_1  = (const float*)d_in[2];
    const float* masks  = (const float*)d_in[3];
    const float* w_ih   = (const float*)d_in[4];
    const float* w_hh   = (const float*)d_in[5];
    const float* b_ih   = (const float*)d_in[6];
    const float* b_hh   = (const float*)d_in[7];
    float* out = (float*)d_out;

    // third output: hxs_1 passthrough
    cudaMemcpyAsync(out + (size_t)(TT * NN + NN) * HH, hxs_1,
                    (size_t)NN * HH * sizeof(float), cudaMemcpyDeviceToDevice);

    // input projections, transposed store (also resets the grid barrier state)
    dim3 g1(G3 / 64, (TT * NN) / 64);   // (24, 128)
    gemm_gi_kernel<<<g1, 256>>>(x, w_ih, b_ih);

    // persistent scan
    size_t shmem = (size_t)(32 * 514 + 24 * 516 + 128 * 6) * sizeof(float);  // 118,400 B
    cudaFuncSetAttribute(gru_scan_kernel,
                         cudaFuncAttributeMaxDynamicSharedMemorySize, (int)shmem);
    gru_scan_kernel<<<SCAN_CTAS, 256, shmem>>>(hxs, masks, w_hh, b_hh, out);
}

// round 3
// speedup vs baseline: 1.8218x; 1.1970x over previous
#include <cuda_runtime.h>
#include <cstdint>
#include <math.h>

// Problem dims
#define TT 128
#define NN 64
#define DD 512
#define HH 512
#define G3 1536   // 3*H
#define SCAN_CTAS 128

typedef unsigned long long ull;

// ---------------- packed f32x2 helpers ----------------
__device__ __forceinline__ ull fma2(ull a, ull b, ull c) {
    ull d;
    asm("fma.rn.f32x2 %0, %1, %2, %3;" : "=l"(d) : "l"(a), "l"(b), "l"(c));
    return d;
}
__device__ __forceinline__ float lo32(ull v) { return __uint_as_float((unsigned)(v & 0xffffffffu)); }
__device__ __forceinline__ float hi32(ull v) { return __uint_as_float((unsigned)(v >> 32)); }
__device__ __forceinline__ ull pack2(float x, float y) {
    return (((ull)__float_as_uint(y)) << 32) | (ull)__float_as_uint(x);
}

// ---------------- global scratch ----------------
// gi stored [m][g]: g_gi[m * 1536 + g]
__device__ float g_gi[(size_t)TT * NN * G3];

struct __align__(128) PadU { unsigned v; unsigned pad[31]; };
__device__ PadU g_count;
__device__ PadU g_epoch;

// =====================================================================
// Kernel 1: gi[m, g] = sum_k x[m,k] * w_ih[g,k] + b_ih[g]
// Tiles 64(m) x 64(g), BK=32, 256 threads, 4x4 f2 thread tile.
// tx -> g (store coalesced in g), ty -> m.
// =====================================================================
__global__ void __launch_bounds__(256, 2) gemm_gi_kernel(
    const float* __restrict__ x,
    const float* __restrict__ w_ih,
    const float* __restrict__ b_ih)
{
    if (blockIdx.x == 0 && blockIdx.y == 0 && threadIdx.x == 0) {
        g_count.v = 0;
        g_epoch.v = 0;
    }

    __shared__ ull Gs[64 * 17];   // w_ih rows (g)
    __shared__ ull Ms[64 * 17];   // x rows (m)

    const int tid = threadIdx.x;
    const int g0 = blockIdx.x * 64;
    const int m0 = blockIdx.y * 64;
    const int tx = tid & 15;      // -> g group
    const int ty = tid >> 4;      // -> m group

    ull acc[4][4];
#pragma unroll
    for (int i = 0; i < 4; i++)
#pragma unroll
        for (int j = 0; j < 4; j++) acc[i][j] = 0ull;

    for (int k0 = 0; k0 < DD; k0 += 32) {
#pragma unroll
        for (int i = 0; i < 2; i++) {
            int s = tid + i * 256;
            int row = s >> 3, kq = s & 7;
            float4 vg = *reinterpret_cast<const float4*>(&w_ih[(size_t)(g0 + row) * DD + k0 + kq * 4]);
            Gs[row * 17 + kq * 2]     = pack2(vg.x, vg.y);
            Gs[row * 17 + kq * 2 + 1] = pack2(vg.z, vg.w);
            float4 vm = *reinterpret_cast<const float4*>(&x[(size_t)(m0 + row) * DD + k0 + kq * 4]);
            Ms[row * 17 + kq * 2]     = pack2(vm.x, vm.y);
            Ms[row * 17 + kq * 2 + 1] = pack2(vm.z, vm.w);
        }
        __syncthreads();

#pragma unroll
        for (int kk = 0; kk < 16; kk++) {
            ull a[4], b[4];
#pragma unroll
            for (int i = 0; i < 4; i++) a[i] = Ms[(ty + 16 * i) * 17 + kk];
#pragma unroll
            for (int j = 0; j < 4; j++) b[j] = Gs[(tx + 16 * j) * 17 + kk];
#pragma unroll
            for (int i = 0; i < 4; i++)
#pragma unroll
                for (int j = 0; j < 4; j++)
                    acc[i][j] = fma2(a[i], b[j], acc[i][j]);
        }
        __syncthreads();
    }

    float bias[4];
#pragma unroll
    for (int j = 0; j < 4; j++) bias[j] = b_ih[g0 + tx + 16 * j];
#pragma unroll
    for (int i = 0; i < 4; i++) {
        int m = m0 + ty + 16 * i;
#pragma unroll
        for (int j = 0; j < 4; j++) {
            int g = g0 + tx + 16 * j;
            g_gi[(size_t)m * G3 + g] = lo32(acc[i][j]) + hi32(acc[i][j]) + bias[j];
        }
    }
}

// =====================================================================
// Kernel 2: persistent GRU scan.
// 128 CTAs: jb = blockIdx&63 (dims jb*8..+7), rb = blockIdx>>6 (rows rb*32..+31).
// 256 threads: ks = tid>>4 (K slice 0..15), pos = tid&15: rg = pos>>2, dg = pos&3.
// Thread tile: 8 rows (rg+4i) x 2 dims (dg*2+dd) x 3 gates = 48 f2 accumulators.
// K strided: kf2 = ks + 16*kk, kk = 0..15.
// Reduce via smem (float-collapsed), epilogue 1 output per thread.
// =====================================================================
__global__ void __launch_bounds__(256) gru_scan_kernel(
    const float* __restrict__ hxs,
    const float* __restrict__ masks,
    const float* __restrict__ w_hh,
    const float* __restrict__ b_hh,
    float* __restrict__ out)
{
    extern __shared__ float smem[];
    float* hs  = smem;                            // [32][514]
    float* ws  = smem + 32 * 514;                 // [24][516]
    float* red = smem + 32 * 514 + 24 * 516;      // [48][260]

    const int tid = threadIdx.x;
    const int jb = blockIdx.x & 63;
    const int rb = blockIdx.x >> 6;
    const int n0 = rb * 32;
    const int ks = tid >> 4;          // 0..15
    const int pos = tid & 15;
    const int rg = pos >> 2;          // 0..3
    const int dg = pos & 3;           // 0..3

    // epilogue mapping: 1 output per thread
    const int e_dim = tid & 7;            // 0..7 local dim
    const int e_rloc = tid >> 3;          // 0..31 local row
    const int e_dimg = jb * 8 + e_dim;    // global dim
    const int e_i  = e_rloc >> 2;
    const int e_rg = e_rloc & 3;
    const int e_dg = e_dim >> 1;
    const int e_dd = e_dim & 1;
    const int e_pcol = e_rg * 4 + e_dg;   // pos column in red

    // ---- stage w_hh slice once: rows g*512 + jb*8 + dloc ----
#pragma unroll
    for (int i = 0; i < 12; i++) {
        int s = tid + i * 256;        // 24 rows x 128 float4
        int lrow = s >> 7;
        int kq = s & 127;
        int g = lrow >> 3;
        int dloc = lrow & 7;
        float4 v = *reinterpret_cast<const float4*>(
            &w_hh[(size_t)(g * HH + jb * 8 + dloc) * HH + kq * 4]);
        *reinterpret_cast<float4*>(&ws[lrow * 516 + kq * 4]) = v;
    }
    const float bh_r = b_hh[e_dimg];
    const float bh_z = b_hh[HH + e_dimg];
    const float bh_n = b_hh[2 * HH + e_dimg];

    const ull* hs_u = reinterpret_cast<const ull*>(hs);
    const ull* ws_u = reinterpret_cast<const ull*>(ws);
    const ull* hp = hs_u + rg * 257 + ks;
    int woff[6];
#pragma unroll
    for (int c = 0; c < 6; c++) {
        int g = c >> 1, dd = c & 1;
        woff[c] = (g * 8 + dg * 2 + dd) * 258 + ks;
    }

    for (int t = 0; t < TT; t++) {
        const float* hprev = (t == 0) ? hxs : (out + (size_t)(t - 1) * NN * HH);

        // ---- prefetch epilogue operands (independent of the dot) ----
        const int e_n = n0 + e_rloc;
        const int e_mm = t * NN + e_n;
        const float e_m = __ldg(&masks[e_mm]);
        const float* gi = g_gi + (size_t)e_mm * G3;
        const float e_ir  = __ldg(&gi[e_dimg]);
        const float e_iz  = __ldg(&gi[HH + e_dimg]);
        const float e_inn = __ldg(&gi[2 * HH + e_dimg]);

        // ---- stage h (unmasked): 32 rows x 512 floats ----
#pragma unroll
        for (int i = 0; i < 16; i++) {
            int s = tid + i * 256;
            int row = s >> 7;
            int kq = s & 127;
            float4 v = __ldcg(reinterpret_cast<const float4*>(
                &hprev[(size_t)(n0 + row) * HH + kq * 4]));
            float2* dst = reinterpret_cast<float2*>(&hs[row * 514 + kq * 4]);
            dst[0] = make_float2(v.x, v.y);
            dst[1] = make_float2(v.z, v.w);
        }
        __syncthreads();

        // ---- register-tiled dot: 8 rows x 6 gate-cols, 16 k-slices ----
        ull acc[48];
#pragma unroll
        for (int s = 0; s < 48; s++) acc[s] = 0ull;

#pragma unroll 4
        for (int kk = 0; kk < 16; kk++) {
            const int ko = kk * 16;
            ull a[8];
#pragma unroll
            for (int i = 0; i < 8; i++) a[i] = hp[i * (4 * 257) + ko];
            ull w[6];
#pragma unroll
            for (int c = 0; c < 6; c++) w[c] = ws_u[woff[c] + ko];
#pragma unroll
            for (int i = 0; i < 8; i++)
#pragma unroll
                for (int c = 0; c < 6; c++)
                    acc[i * 6 + c] = fma2(a[i], w[c], acc[i * 6 + c]);
        }

        // ---- write partials (float-collapsed) ----
#pragma unroll
        for (int s = 0; s < 48; s++)
            red[s * 260 + tid] = lo32(acc[s]) + hi32(acc[s]);
        __syncthreads();

        // ---- epilogue: reduce over 16 k-slices, gates, store ----
        {
            float pr = 0.f, pz = 0.f, pn = 0.f;
            const int sr = (e_i * 6 + 0 + e_dd) * 260 + e_pcol;
            const int sz = (e_i * 6 + 2 + e_dd) * 260 + e_pcol;
            const int sn = (e_i * 6 + 4 + e_dd) * 260 + e_pcol;
#pragma unroll
            for (int k = 0; k < 16; k++) {
                pr += red[sr + k * 16];
                pz += red[sz + k * 16];
                pn += red[sn + k * 16];
            }
            float ghr = pr * e_m + bh_r;
            float ghz = pz * e_m + bh_z;
            float ghn = pn * e_m + bh_n;

            float r = 1.0f / (1.0f + expf(-(e_ir + ghr)));
            float z = 1.0f / (1.0f + expf(-(e_iz + ghz)));
            float nc = tanhf(e_inn + r * ghn);
            float hval = e_m * hs[e_rloc * 514 + e_dimg];
            float hnew = (1.0f - z) * nc + z * hval;

            out[(size_t)e_mm * HH + e_dimg] = hnew;
            if (t == TT - 1)
                out[(size_t)TT * NN * HH + (size_t)e_n * HH + e_dimg] = hnew;
        }

        // ---- grid barrier (skip after last step) ----
        if (t < TT - 1) {
            __syncthreads();
            if (tid == 0) {
                unsigned old;
                asm volatile("atom.add.release.gpu.global.u32 %0, [%1], 1;"
                             : "=r"(old) : "l"(&g_count.v) : "memory");
                unsigned target = (unsigned)(t + 1);
                if (old == SCAN_CTAS - 1) {
                    g_count.v = 0;
                    asm volatile("st.release.gpu.global.u32 [%0], %1;"
                                 :: "l"(&g_epoch.v), "r"(target) : "memory");
                } else {
                    unsigned e;
                    do {
                        asm volatile("ld.acquire.gpu.global.u32 %0, [%1];"
                                     : "=r"(e) : "l"(&g_epoch.v) : "memory");
                    } while (e < target);
                }
            }
            __syncthreads();
        }
    }
}

// =====================================================================
extern "C" void kernel_launch(void* const* d_in, const int* in_sizes, int n_in,
                              void* d_out, int out_size)
{
    const float* x      = (const float*)d_in[0];
    const float* hxs    = (const float*)d_in[1];
    const float* hxs_1  = (const float*)d_in[2];
    const float* masks  = (const float*)d_in[3];
    const float* w_ih   = (const float*)d_in[4];
    const float* w_hh   = (const float*)d_in[5];
    const float* b_ih   = (const float*)d_in[6];
    const float* b_hh   = (const float*)d_in[7];
    float* out = (float*)d_out;

    // third output: hxs_1 passthrough
    cudaMemcpyAsync(out + (size_t)(TT * NN + NN) * HH, hxs_1,
                    (size_t)NN * HH * sizeof(float), cudaMemcpyDeviceToDevice);

    // input projections (also resets the grid barrier state)
    dim3 g1(G3 / 64, (TT * NN) / 64);   // (24, 128)
    gemm_gi_kernel<<<g1, 256>>>(x, w_ih, b_ih);

    // persistent scan
    size_t shmem = (size_t)(32 * 514 + 24 * 516 + 48 * 260) * sizeof(float);  // 165,248 B
    cudaFuncSetAttribute(gru_scan_kernel,
                         cudaFuncAttributeMaxDynamicSharedMemorySize, (int)shmem);
    gru_scan_kernel<<<SCAN_CTAS, 256, shmem>>>(hxs, masks, w_hh, b_hh, out);
}